// round 2
// baseline (speedup 1.0000x reference)
#include <cuda_runtime.h>

// x is (B=8, C=64, H=512, W=512) fp32; indices = 32 int32 channel ids; k = 3.
#define B_ 8
#define C_ 64
#define H_ 512
#define W_ 512
#define MAXV 10000.0f

__device__ unsigned char g_chan_mask[C_];

__global__ void build_mask_kernel(const int* __restrict__ indices, int n_idx) {
    int t = threadIdx.x;
    if (t < C_) g_chan_mask[t] = 0;
    __syncthreads();
    if (t < n_idx) {
        int c = indices[t];
        if (c >= 0 && c < C_) g_chan_mask[c] = 1;
    }
}

__device__ __forceinline__ float min3(float a, float b, float c) {
    return fminf(fminf(a, b), c);
}

// Each thread produces 8 consecutive outputs (two float4s).
__global__ void __launch_bounds__(256) erode_copy_kernel(
    const float* __restrict__ x, float* __restrict__ out, int total8) {
    int i = blockIdx.x * blockDim.x + threadIdx.x;
    if (i >= total8) return;

    const int HW8 = (H_ * W_) / 8;            // 32768
    int plane = i >> 15;                       // i / HW8
    int c = plane & (C_ - 1);
    int p = i & (HW8 - 1);

    const float4* __restrict__ x4 = (const float4*)x;
    float4* __restrict__ o4 = (float4*)out;

    if (!g_chan_mask[c]) {
        // pass-through copy: two independent 128-bit loads, then two stores
        float4 a = x4[2 * i];
        float4 b = x4[2 * i + 1];
        o4[2 * i] = a;
        o4[2 * i + 1] = b;
        return;
    }

    int h = p >> 6;                            // W/8 = 64 groups per row
    int w = (p & 63) << 3;

    const float* __restrict__ base =
        x + (size_t)plane * (H_ * W_) + (size_t)h * W_ + w;

    // Border rows: clamp pointer to center row; min(x,x)=x is identical to
    // +inf padding for the out-of-range row.
    const float* __restrict__ rm = (h > 0)      ? base - W_ : base;
    const float* __restrict__ rp = (h < H_ - 1) ? base + W_ : base;

    bool hl = (w > 0);
    bool hr = (w + 8 < W_);
    int lo = hl ? -1 : 0;                      // clamped halo offsets (loads are
    int ro = hr ?  8 : 7;                      // always in-bounds; value selected)

    // 12 independent loads, no branches between them — max MLP.
    float4 a0 = *(const float4*)(base);
    float4 a1 = *(const float4*)(base + 4);
    float4 b0 = *(const float4*)(rm);
    float4 b1 = *(const float4*)(rm + 4);
    float4 c0 = *(const float4*)(rp);
    float4 c1 = *(const float4*)(rp + 4);
    float La = base[lo], Lb = rm[lo], Lc = rp[lo];
    float Ra = base[ro], Rb = rm[ro], Rc = rp[ro];

    // vertical min across the (up to) 3 rows, 10 columns [w-1 .. w+8]
    float v0 = hl ? min3(La, Lb, Lc) : MAXV;
    float v1 = min3(a0.x, b0.x, c0.x);
    float v2 = min3(a0.y, b0.y, c0.y);
    float v3 = min3(a0.z, b0.z, c0.z);
    float v4 = min3(a0.w, b0.w, c0.w);
    float v5 = min3(a1.x, b1.x, c1.x);
    float v6 = min3(a1.y, b1.y, c1.y);
    float v7 = min3(a1.z, b1.z, c1.z);
    float v8 = min3(a1.w, b1.w, c1.w);
    float v9 = hr ? min3(Ra, Rb, Rc) : MAXV;

    // horizontal 3-tap min
    float4 o0, o1;
    o0.x = min3(v0, v1, v2);
    o0.y = min3(v1, v2, v3);
    o0.z = min3(v2, v3, v4);
    o0.w = min3(v3, v4, v5);
    o1.x = min3(v4, v5, v6);
    o1.y = min3(v5, v6, v7);
    o1.z = min3(v6, v7, v8);
    o1.w = min3(v7, v8, v9);
    o4[2 * i] = o0;
    o4[2 * i + 1] = o1;
}

extern "C" void kernel_launch(void* const* d_in, const int* in_sizes, int n_in,
                              void* d_out, int out_size) {
    const float* x       = (const float*)d_in[0];
    const int*   indices = (const int*)d_in[1];
    int n_idx = in_sizes[1];
    float* out = (float*)d_out;

    build_mask_kernel<<<1, 64>>>(indices, n_idx);

    int total8 = out_size / 8;                 // 16,777,216
    int blocks = (total8 + 255) / 256;
    erode_copy_kernel<<<blocks, 256>>>(x, out, total8);
}

// round 3
// speedup vs baseline: 1.0700x; 1.0700x over previous
#include <cuda_runtime.h>

// x is (B=8, C=64, H=512, W=512) fp32; indices = 32 int32 channel ids; k = 3.
#define B_ 8
#define C_ 64
#define H_ 512
#define W_ 512
#define MAXV 10000.0f

__device__ unsigned char g_chan_mask[C_];

__global__ void build_mask_kernel(const int* __restrict__ indices, int n_idx) {
    int t = threadIdx.x;
    if (t < C_) g_chan_mask[t] = 0;
    __syncthreads();
    if (t < n_idx) {
        int c = indices[t];
        if (c >= 0 && c < C_) g_chan_mask[c] = 1;
    }
}

__device__ __forceinline__ float min3(float a, float b, float c) {
    return fminf(fminf(a, b), c);
}

// Each thread produces 4 consecutive outputs (one float4).
// Halo columns are exchanged between lanes via warp shuffle of the
// vertical-min values; only lanes 0/31 load true halo data.
__global__ void __launch_bounds__(256) erode_copy_kernel(
    const float* __restrict__ x, float* __restrict__ out, int total4) {
    int i = blockIdx.x * blockDim.x + threadIdx.x;
    if (i >= total4) return;

    const int HW4 = (H_ * W_) / 4;            // 65536 groups per plane
    int plane = i >> 16;                       // i / HW4
    int c = plane & (C_ - 1);
    int p = i & (HW4 - 1);

    const float4* __restrict__ x4 = (const float4*)x;
    float4* __restrict__ o4 = (float4*)out;

    // Warp-uniform: a warp (32 consecutive groups) never straddles a plane.
    if (!g_chan_mask[c]) {
        o4[i] = x4[i];
        return;
    }

    int h = p >> 7;                            // W/4 = 128 groups per row
    int w = (p & 127) << 2;
    int lane = threadIdx.x & 31;

    const float* __restrict__ base =
        x + (size_t)plane * (H_ * W_) + (size_t)h * W_ + w;

    // Border rows: clamp to center row; min(x,x)=x == +inf padding.
    const float* __restrict__ rm = (h > 0)      ? base - W_ : base;
    const float* __restrict__ rp = (h < H_ - 1) ? base + W_ : base;

    // 3 unconditional 128-bit loads (MLP=3, no branches between them).
    float4 a = *(const float4*)base;
    float4 b = *(const float4*)rm;
    float4 d = *(const float4*)rp;

    // Vertical mins of the 4 owned columns.
    float v1 = min3(a.x, b.x, d.x);
    float v2 = min3(a.y, b.y, d.y);
    float v3 = min3(a.z, b.z, d.z);
    float v4 = min3(a.w, b.w, d.w);

    // Halo column vmins from neighbor lanes (warp covers 128 contiguous
    // cols within one row; lanes are consecutive 4-col groups).
    float vl = __shfl_up_sync(0xFFFFFFFFu, v4, 1);   // neighbor's last col
    float vr = __shfl_down_sync(0xFFFFFFFFu, v1, 1); // neighbor's first col

    // Warp-edge lanes: true halo (3 scalar loads) or image border (+inf).
    if (lane == 0) {
        vl = (w > 0) ? min3(base[-1], rm[-1], rp[-1]) : MAXV;
    }
    if (lane == 31) {
        vr = (w + 4 < W_) ? min3(base[4], rm[4], rp[4]) : MAXV;
    }

    // Horizontal 3-tap min.
    float4 o;
    o.x = min3(vl, v1, v2);
    o.y = min3(v1, v2, v3);
    o.z = min3(v2, v3, v4);
    o.w = min3(v3, v4, vr);
    o4[i] = o;
}

extern "C" void kernel_launch(void* const* d_in, const int* in_sizes, int n_in,
                              void* d_out, int out_size) {
    const float* x       = (const float*)d_in[0];
    const int*   indices = (const int*)d_in[1];
    int n_idx = in_sizes[1];
    float* out = (float*)d_out;

    build_mask_kernel<<<1, 64>>>(indices, n_idx);

    int total4 = out_size / 4;                 // 33,554,432
    int blocks = (total4 + 255) / 256;
    erode_copy_kernel<<<blocks, 256>>>(x, out, total4);
}

// round 4
// speedup vs baseline: 1.1803x; 1.1031x over previous
#include <cuda_runtime.h>

// x is (B=8, C=64, H=512, W=512) fp32; indices = 32 int32 channel ids; k = 3.
#define B_ 8
#define C_ 64
#define H_ 512
#define W_ 512
#define MAXV 10000.0f

__device__ unsigned char g_chan_mask[C_];

__global__ void build_mask_kernel(const int* __restrict__ indices, int n_idx) {
    int t = threadIdx.x;
    if (t < C_) g_chan_mask[t] = 0;
    __syncthreads();
    if (t < n_idx) {
        int c = indices[t];
        if (c >= 0 && c < C_) g_chan_mask[c] = 1;
    }
}

__device__ __forceinline__ float min3(float a, float b, float c) {
    return fminf(fminf(a, b), c);
}

// Each thread produces a 4-col x 2-row patch (8 outputs).
// Erode path: 4 row loads (rows h-1..h+2, clamped) serve BOTH output rows.
// Halo columns come from neighbor lanes via shuffle of the vertical mins;
// only lanes 0/31 do real halo loads.
__global__ void __launch_bounds__(256, 8) erode_copy_kernel(
    const float* __restrict__ x, float* __restrict__ out, int total8) {
    int i = blockIdx.x * blockDim.x + threadIdx.x;
    if (i >= total8) return;

    const int GP = (H_ / 2) * (W_ / 4);       // 32768 patches per plane
    int plane = i >> 15;
    int c = plane & (C_ - 1);
    int p = i & (GP - 1);

    int hp = p >> 7;                           // row-pair index (0..255)
    int h  = hp << 1;
    int w4 = p & 127;
    int w  = w4 << 2;

    const float4* __restrict__ x4 = (const float4*)x;
    float4* __restrict__ o4 = (float4*)out;

    // Warp-uniform branch: a warp = 32 consecutive w4 groups = one row pair
    // of one plane; never straddles planes.
    int idx0 = (plane << 16) + (h << 7) + w4;  // float4 index of row h
    int idx1 = idx0 + 128;                     // row h+1

    if (!g_chan_mask[c]) {
        float4 u = x4[idx0];
        float4 v = x4[idx1];
        o4[idx0] = u;
        o4[idx1] = v;
        return;
    }

    int lane = threadIdx.x & 31;

    const float* __restrict__ r1 =
        x + (size_t)plane * (H_ * W_) + (size_t)h * W_ + w;      // row h
    const float* __restrict__ r2 = r1 + W_;                       // row h+1
    const float* __restrict__ r0 = (h > 0)       ? r1 - W_ : r1;  // row h-1 (clamped)
    const float* __restrict__ r3 = (h + 2 < H_)  ? r2 + W_ : r2;  // row h+2 (clamped)

    // 4 unconditional 128-bit loads serving both output rows.
    float4 a = *(const float4*)r0;
    float4 b = *(const float4*)r1;
    float4 d = *(const float4*)r2;
    float4 e = *(const float4*)r3;

    // Vertical mins: row h uses (r0,r1,r2); row h+1 uses (r1,r2,r3).
    float m1 = fminf(b.x, d.x), m2 = fminf(b.y, d.y);
    float m3 = fminf(b.z, d.z), m4 = fminf(b.w, d.w);
    float A1 = fminf(m1, a.x), A2 = fminf(m2, a.y);
    float A3 = fminf(m3, a.z), A4 = fminf(m4, a.w);
    float B1 = fminf(m1, e.x), B2 = fminf(m2, e.y);
    float B3 = fminf(m3, e.z), B4 = fminf(m4, e.w);

    // Halo vmins from neighbor lanes.
    float Al = __shfl_up_sync(0xFFFFFFFFu, A4, 1);
    float Ar = __shfl_down_sync(0xFFFFFFFFu, A1, 1);
    float Bl = __shfl_up_sync(0xFFFFFFFFu, B4, 1);
    float Br = __shfl_down_sync(0xFFFFFFFFu, B1, 1);

    if (lane == 0) {
        if (w > 0) {
            float h0 = r0[-1], h1 = r1[-1], h2 = r2[-1], h3 = r3[-1];
            float hm = fminf(h1, h2);
            Al = fminf(hm, h0);
            Bl = fminf(hm, h3);
        } else {
            Al = MAXV; Bl = MAXV;
        }
    }
    if (lane == 31) {
        if (w + 4 < W_) {
            float h0 = r0[4], h1 = r1[4], h2 = r2[4], h3 = r3[4];
            float hm = fminf(h1, h2);
            Ar = fminf(hm, h0);
            Br = fminf(hm, h3);
        } else {
            Ar = MAXV; Br = MAXV;
        }
    }

    // Horizontal 3-tap mins.
    float4 oA, oB;
    oA.x = min3(Al, A1, A2);
    oA.y = min3(A1, A2, A3);
    oA.z = min3(A2, A3, A4);
    oA.w = min3(A3, A4, Ar);
    oB.x = min3(Bl, B1, B2);
    oB.y = min3(B1, B2, B3);
    oB.z = min3(B2, B3, B4);
    oB.w = min3(B3, B4, Br);
    o4[idx0] = oA;
    o4[idx1] = oB;
}

extern "C" void kernel_launch(void* const* d_in, const int* in_sizes, int n_in,
                              void* d_out, int out_size) {
    const float* x       = (const float*)d_in[0];
    const int*   indices = (const int*)d_in[1];
    int n_idx = in_sizes[1];
    float* out = (float*)d_out;

    build_mask_kernel<<<1, 64>>>(indices, n_idx);

    int total8 = out_size / 8;                 // 16,777,216 patches
    int blocks = (total8 + 255) / 256;         // 65536 blocks
    erode_copy_kernel<<<blocks, 256>>>(x, out, total8);
}

// round 5
// speedup vs baseline: 1.1847x; 1.0037x over previous
#include <cuda_runtime.h>

// x is (B=8, C=64, H=512, W=512) fp32; indices = 32 int32 channel ids; k = 3.
#define B_ 8
#define C_ 64
#define H_ 512
#define W_ 512
#define MAXV 10000.0f

__device__ __forceinline__ float min3(float a, float b, float c) {
    return fminf(fminf(a, b), c);
}

// Each thread produces a 4-col x 2-row patch (8 outputs).
// Channel membership is decided per-warp via a ballot over the indices
// array (warp-uniform; one L1-resident LDG per lane). No mask kernel.
__global__ void __launch_bounds__(256, 8) erode_copy_kernel(
    const float* __restrict__ x, float* __restrict__ out,
    const int* __restrict__ indices, int n_idx, int total8) {
    int i = blockIdx.x * blockDim.x + threadIdx.x;
    if (i >= total8) return;

    const int GP = (H_ / 2) * (W_ / 4);       // 32768 patches per plane
    int plane = i >> 15;
    int c = plane & (C_ - 1);
    int p = i & (GP - 1);

    int hp = p >> 7;                           // row-pair index (0..255)
    int h  = hp << 1;
    int w4 = p & 127;
    int w  = w4 << 2;

    int lane = threadIdx.x & 31;

    // Warp-uniform membership test: indices has 32 entries (tiny, L1-hot).
    int idx_val = (lane < n_idx) ? __ldg(&indices[lane]) : -1;
    unsigned hit = __ballot_sync(0xFFFFFFFFu, idx_val == c);

    const float4* __restrict__ x4 = (const float4*)x;
    float4* __restrict__ o4 = (float4*)out;

    int idx0 = (plane << 16) + (h << 7) + w4;  // float4 index of row h
    int idx1 = idx0 + 128;                     // row h+1

    if (!hit) {
        // pass-through copy; streaming hints (no reuse either side)
        float4 u = __ldcs(&x4[idx0]);
        float4 v = __ldcs(&x4[idx1]);
        __stcs(&o4[idx0], u);
        __stcs(&o4[idx1], v);
        return;
    }

    const float* __restrict__ r1 =
        x + (size_t)plane * (H_ * W_) + (size_t)h * W_ + w;      // row h
    const float* __restrict__ r2 = r1 + W_;                       // row h+1
    const float* __restrict__ r0 = (h > 0)       ? r1 - W_ : r1;  // row h-1 (clamped)
    const float* __restrict__ r3 = (h + 2 < H_)  ? r2 + W_ : r2;  // row h+2 (clamped)

    // 4 unconditional 128-bit loads serving both output rows.
    float4 a = *(const float4*)r0;
    float4 b = *(const float4*)r1;
    float4 d = *(const float4*)r2;
    float4 e = *(const float4*)r3;

    // Vertical mins: row h uses (r0,r1,r2); row h+1 uses (r1,r2,r3).
    float m1 = fminf(b.x, d.x), m2 = fminf(b.y, d.y);
    float m3 = fminf(b.z, d.z), m4 = fminf(b.w, d.w);
    float A1 = fminf(m1, a.x), A2 = fminf(m2, a.y);
    float A3 = fminf(m3, a.z), A4 = fminf(m4, a.w);
    float B1 = fminf(m1, e.x), B2 = fminf(m2, e.y);
    float B3 = fminf(m3, e.z), B4 = fminf(m4, e.w);

    // Halo vmins from neighbor lanes (warp = 128 contiguous cols, one row pair).
    float Al = __shfl_up_sync(0xFFFFFFFFu, A4, 1);
    float Ar = __shfl_down_sync(0xFFFFFFFFu, A1, 1);
    float Bl = __shfl_up_sync(0xFFFFFFFFu, B4, 1);
    float Br = __shfl_down_sync(0xFFFFFFFFu, B1, 1);

    if (lane == 0) {
        if (w > 0) {
            float h0 = r0[-1], h1 = r1[-1], h2 = r2[-1], h3 = r3[-1];
            float hm = fminf(h1, h2);
            Al = fminf(hm, h0);
            Bl = fminf(hm, h3);
        } else {
            Al = MAXV; Bl = MAXV;
        }
    }
    if (lane == 31) {
        if (w + 4 < W_) {
            float h0 = r0[4], h1 = r1[4], h2 = r2[4], h3 = r3[4];
            float hm = fminf(h1, h2);
            Ar = fminf(hm, h0);
            Br = fminf(hm, h3);
        } else {
            Ar = MAXV; Br = MAXV;
        }
    }

    // Horizontal 3-tap mins.
    float4 oA, oB;
    oA.x = min3(Al, A1, A2);
    oA.y = min3(A1, A2, A3);
    oA.z = min3(A2, A3, A4);
    oA.w = min3(A3, A4, Ar);
    oB.x = min3(Bl, B1, B2);
    oB.y = min3(B1, B2, B3);
    oB.z = min3(B2, B3, B4);
    oB.w = min3(B3, B4, Br);
    __stcs(&o4[idx0], oA);
    __stcs(&o4[idx1], oB);
}

extern "C" void kernel_launch(void* const* d_in, const int* in_sizes, int n_in,
                              void* d_out, int out_size) {
    const float* x       = (const float*)d_in[0];
    const int*   indices = (const int*)d_in[1];
    int n_idx = in_sizes[1];
    float* out = (float*)d_out;

    int total8 = out_size / 8;                 // 16,777,216 patches
    int blocks = (total8 + 255) / 256;         // 65536 blocks
    erode_copy_kernel<<<blocks, 256>>>(x, out, indices, n_idx, total8);
}

// round 6
// speedup vs baseline: 1.1936x; 1.0076x over previous
#include <cuda_runtime.h>

// x is (B=8, C=64, H=512, W=512) fp32; indices = 32 int32 channel ids; k = 3.
#define B_ 8
#define C_ 64
#define H_ 512
#define W_ 512
#define MAXV 10000.0f

__device__ __forceinline__ float min3(float a, float b, float c) {
    return fminf(fminf(a, b), c);
}

// Each thread produces a 4-col x 4-row patch (16 outputs).
// Erode path: 6 row loads (rows h-1..h+4, clamped) serve all 4 output rows.
// Halo columns exchanged via warp shuffle of vertical mins; lanes 0/31 load
// the true halo (6 scalars each).
__global__ void __launch_bounds__(256) erode_copy_kernel(
    const float* __restrict__ x, float* __restrict__ out,
    const int* __restrict__ indices, int n_idx, int total16) {
    int i = blockIdx.x * blockDim.x + threadIdx.x;
    if (i >= total16) return;

    const int GP = (H_ / 4) * (W_ / 4);       // 16384 patches per plane
    int plane = i >> 14;
    int c = plane & (C_ - 1);
    int p = i & (GP - 1);

    int hq = p >> 7;                           // row-quad index (0..127)
    int h  = hq << 2;
    int w4 = p & 127;
    int w  = w4 << 2;

    int lane = threadIdx.x & 31;

    // Warp-uniform membership test (indices: 32 entries, L1-hot).
    int idx_val = (lane < n_idx) ? __ldg(&indices[lane]) : -1;
    unsigned hit = __ballot_sync(0xFFFFFFFFu, idx_val == c);

    const float4* __restrict__ x4 = (const float4*)x;
    float4* __restrict__ o4 = (float4*)out;

    int idx0 = (plane << 16) + (h << 7) + w4;  // float4 index of row h

    if (!hit) {
        float4 u0 = x4[idx0];
        float4 u1 = x4[idx0 + 128];
        float4 u2 = x4[idx0 + 256];
        float4 u3 = x4[idx0 + 384];
        __stcs(&o4[idx0],       u0);
        __stcs(&o4[idx0 + 128], u1);
        __stcs(&o4[idx0 + 256], u2);
        __stcs(&o4[idx0 + 384], u3);
        return;
    }

    const float* __restrict__ r1 =
        x + (size_t)plane * (H_ * W_) + (size_t)h * W_ + w;       // row h
    const float* __restrict__ r2 = r1 + W_;                        // h+1
    const float* __restrict__ r3 = r2 + W_;                        // h+2
    const float* __restrict__ r4 = r3 + W_;                        // h+3
    const float* __restrict__ r0 = (h > 0)      ? r1 - W_ : r1;    // h-1 (clamped)
    const float* __restrict__ r5 = (h + 4 < H_) ? r4 + W_ : r4;    // h+4 (clamped)

    // 6 unconditional 128-bit loads serving all 4 output rows.
    float4 a = *(const float4*)r0;
    float4 b = *(const float4*)r1;
    float4 g = *(const float4*)r2;
    float4 d = *(const float4*)r3;
    float4 e = *(const float4*)r4;
    float4 f = *(const float4*)r5;

    // Vertical mins. Output rows: A=h (r0,r1,r2), B=h+1 (r1,r2,r3),
    // C=h+2 (r2,r3,r4), D=h+3 (r3,r4,r5).
    float A1, A2, A3, A4, B1, B2, B3, B4, C1, C2, C3, C4, D1, D2, D3, D4;
    {
        float p01, p12, p23;
        p01 = fminf(b.x, g.x); p12 = fminf(g.x, d.x); p23 = fminf(d.x, e.x);
        A1 = fminf(a.x, p01); B1 = fminf(b.x, p12);
        C1 = fminf(g.x, p23); D1 = fminf(p23, f.x);
        p01 = fminf(b.y, g.y); p12 = fminf(g.y, d.y); p23 = fminf(d.y, e.y);
        A2 = fminf(a.y, p01); B2 = fminf(b.y, p12);
        C2 = fminf(g.y, p23); D2 = fminf(p23, f.y);
        p01 = fminf(b.z, g.z); p12 = fminf(g.z, d.z); p23 = fminf(d.z, e.z);
        A3 = fminf(a.z, p01); B3 = fminf(b.z, p12);
        C3 = fminf(g.z, p23); D3 = fminf(p23, f.z);
        p01 = fminf(b.w, g.w); p12 = fminf(g.w, d.w); p23 = fminf(d.w, e.w);
        A4 = fminf(a.w, p01); B4 = fminf(b.w, p12);
        C4 = fminf(g.w, p23); D4 = fminf(p23, f.w);
    }

    // Halo vmins from neighbor lanes (warp = 128 contiguous cols, one row quad).
    float Al = __shfl_up_sync(0xFFFFFFFFu, A4, 1);
    float Bl = __shfl_up_sync(0xFFFFFFFFu, B4, 1);
    float Cl = __shfl_up_sync(0xFFFFFFFFu, C4, 1);
    float Dl = __shfl_up_sync(0xFFFFFFFFu, D4, 1);
    float Ar = __shfl_down_sync(0xFFFFFFFFu, A1, 1);
    float Br = __shfl_down_sync(0xFFFFFFFFu, B1, 1);
    float Cr = __shfl_down_sync(0xFFFFFFFFu, C1, 1);
    float Dr = __shfl_down_sync(0xFFFFFFFFu, D1, 1);

    if (lane == 0) {
        if (w > 0) {
            float h0 = r0[-1], h1 = r1[-1], h2 = r2[-1];
            float h3 = r3[-1], h4 = r4[-1], h5 = r5[-1];
            float q12 = fminf(h1, h2), q23 = fminf(h2, h3), q34 = fminf(h3, h4);
            Al = fminf(h0, q12);
            Bl = fminf(h1, q23);
            Cl = fminf(q23, h4); // min(h2,h3,h4)
            Dl = fminf(q34, h5);
        } else {
            Al = MAXV; Bl = MAXV; Cl = MAXV; Dl = MAXV;
        }
    }
    if (lane == 31) {
        if (w + 4 < W_) {
            float h0 = r0[4], h1 = r1[4], h2 = r2[4];
            float h3 = r3[4], h4 = r4[4], h5 = r5[4];
            float q12 = fminf(h1, h2), q23 = fminf(h2, h3), q34 = fminf(h3, h4);
            Ar = fminf(h0, q12);
            Br = fminf(h1, q23);
            Cr = fminf(q23, h4);
            Dr = fminf(q34, h5);
        } else {
            Ar = MAXV; Br = MAXV; Cr = MAXV; Dr = MAXV;
        }
    }

    // Horizontal 3-tap mins, one float4 store per output row.
    float4 o;
    o.x = min3(Al, A1, A2); o.y = min3(A1, A2, A3);
    o.z = min3(A2, A3, A4); o.w = min3(A3, A4, Ar);
    __stcs(&o4[idx0], o);
    o.x = min3(Bl, B1, B2); o.y = min3(B1, B2, B3);
    o.z = min3(B2, B3, B4); o.w = min3(B3, B4, Br);
    __stcs(&o4[idx0 + 128], o);
    o.x = min3(Cl, C1, C2); o.y = min3(C1, C2, C3);
    o.z = min3(C2, C3, C4); o.w = min3(C3, C4, Cr);
    __stcs(&o4[idx0 + 256], o);
    o.x = min3(Dl, D1, D2); o.y = min3(D1, D2, D3);
    o.z = min3(D2, D3, D4); o.w = min3(D3, D4, Dr);
    __stcs(&o4[idx0 + 384], o);
}

extern "C" void kernel_launch(void* const* d_in, const int* in_sizes, int n_in,
                              void* d_out, int out_size) {
    const float* x       = (const float*)d_in[0];
    const int*   indices = (const int*)d_in[1];
    int n_idx = in_sizes[1];
    float* out = (float*)d_out;

    int total16 = out_size / 16;               // 8,388,608 patches
    int blocks = (total16 + 255) / 256;        // 32768 blocks
    erode_copy_kernel<<<blocks, 256>>>(x, out, indices, n_idx, total16);
}